// round 14
// baseline (speedup 1.0000x reference)
#include <cuda_runtime.h>
#include <math.h>
#include <stdint.h>

// Shapes: output1 (4,1024,3), output2 (4,4096,3), gt (4,4096,3)
#define BATCH 4
#define NP1 1024
#define NP2 4096
// log2(e)/eps, eps = 0.005
#define K2F 288.5390081777927f
// eps*ln(2)
#define EPSLN2F 0.0034657359027997265f

// scratch (__device__ globals). Every buffer fully written before read
// within one call — no cross-call state, no atomics, no stream/event objects.
__device__ float d_gtfps[BATCH * NP1 * 3];
__device__ float d_seeds1[BATCH * 51 * 3];
__device__ float d_seeds2[BATCH * 204 * 3];
__device__ float d_f1[BATCH * NP1];
__device__ float d_g1[BATCH * NP1];
__device__ float d_f2[BATCH * NP2];
__device__ float d_g2[BATCH * NP2];
__device__ float d_emdpart[2 * BATCH * 128];
__device__ float d_chpart[4 * BATCH * 16 * 2];
__device__ float d_upart1[BATCH * 7 * 8];
__device__ float d_upart2[BATCH * 26 * 8];

__device__ __forceinline__ float ex2f(float x) {
    float y; asm("ex2.approx.f32 %0, %1;" : "=f"(y) : "f"(x)); return y;
}
__device__ __forceinline__ float lg2f(float x) {
    float y; asm("lg2.approx.f32 %0, %1;" : "=f"(y) : "f"(x)); return y;
}

// Lowering helpers (validated — uniform loss is knife-edge, frozen).
__device__ __forceinline__ float norm_plain(float x, float y, float z) {
    return __fadd_rn(__fadd_rn(__fmul_rn(x, x), __fmul_rn(y, y)), __fmul_rn(z, z));
}
__device__ __forceinline__ float norm_asc(float x, float y, float z) {
    return fmaf(z, z, fmaf(y, y, __fmul_rn(x, x)));
}
__device__ __forceinline__ float dot_asc(float x, float y, float z,
                                         float qx, float qy, float qz) {
    return fmaf(z, qz, fmaf(y, qy, __fmul_rn(x, qx)));
}
__device__ __forceinline__ float sqd_ref(float an, float bn, float dot) {
    float d = fmaf(-2.f, dot, __fadd_rn(an, bn));
    return fmaxf(d, 0.f);
}

// ---------------------------------------------------------------------------
// FPS v3: low-latency argmax loop.
//  - per-lane best (dist,idx) identical semantics to validated version
//  - warp reduce: redux.max on dist bits (floats >= 0, monotonic as u32),
//    then redux.min on candidate idx among dist==max  -> identical winner
//  - cross-warp: 8 u64 keys (dist<<32 | N-idx) in smem, ALL threads scan
//    (broadcast reads) -> no serial tid0 step; double-buffered -> 1 barrier.
// Seeds bit-identical to R13.
// ---------------------------------------------------------------------------
template <int PP, int FORM>
__global__ void __launch_bounds__(256) fps3_kernel(const float* __restrict__ pcd,
                                                   int npoint,
                                                   float* __restrict__ outc) {
    const int NT = 256;
    const int N = PP * NT;
    int b = blockIdx.x;
    int tid = threadIdx.x;
    int lane = tid & 31, wid = tid >> 5;
    const float* Pb = pcd + (size_t)b * N * 3;

    float px[PP], py[PP], pz[PP], dd[PP];
#pragma unroll
    for (int k = 0; k < PP; k++) {
        int idx = tid + k * NT;
        px[k] = Pb[3 * idx]; py[k] = Pb[3 * idx + 1]; pz[k] = Pb[3 * idx + 2];
        dd[k] = 1e10f;
    }

    __shared__ unsigned long long wk[2][8];
    int far = 0;

    for (int it = 0; it < npoint; ++it) {
        float cx = Pb[3 * far], cy = Pb[3 * far + 1], cz = Pb[3 * far + 2];
        if (tid == 0) {
            float* o = outc + ((size_t)b * npoint + it) * 3;
            o[0] = cx; o[1] = cy; o[2] = cz;
        }
        float bv = -1.f; int bi = N;
#pragma unroll
        for (int k = 0; k < PP; k++) {
            float dx = __fadd_rn(px[k], -cx);
            float dy = __fadd_rn(py[k], -cy);
            float dz = __fadd_rn(pz[k], -cz);
            float d;
            if (FORM == 0)
                d = fmaf(dz, dz, fmaf(dy, dy, __fmul_rn(dx, dx)));
            else
                d = fmaf(dx, dx, fmaf(dy, dy, __fmul_rn(dz, dz)));
            float nd = fminf(dd[k], d);
            dd[k] = nd;
            int idx = tid + k * NT;
            if (nd > bv || (nd == bv && idx < bi)) { bv = nd; bi = idx; }
        }
        // warp argmax: max dist, then min idx among ties
        unsigned ud = __float_as_uint(bv);         // bv >= 0 after PP loop
        unsigned um = __reduce_max_sync(0xffffffffu, ud);
        unsigned cand = (ud == um) ? (unsigned)bi : 0x7fffffffu;
        unsigned bw = __reduce_min_sync(0xffffffffu, cand);
        if (lane == 0)
            wk[it & 1][wid] = ((unsigned long long)um << 32) |
                              (unsigned)(N - (int)bw);
        __syncthreads();
        unsigned long long m = wk[it & 1][0];
#pragma unroll
        for (int w = 1; w < 8; w++) {
            unsigned long long o = wk[it & 1][w];
            m = o > m ? o : m;
        }
        far = N - (int)(m & 0xFFFFFFFFull);
    }
}

// ---------------------------------------------------------------------------
// Fused Sinkhorn half-iteration: one launch advances BOTH chains
// (emd1: N1=1024, emd2: N2=4096). Blocks x < N1/32 serve chain 1.
// Warp-per-column: warp w owns column bx*32+w; lanes stride points by 32;
// butterfly-shfl max then sum (no block-wide reduction barriers).
// smem record (x,y,z,hw), hw = hk - K2F*|p|^2:
//   a = fma(x,qx2, fma(y,qy2, fma(z,qz2, hw + c)))
// ---------------------------------------------------------------------------
__global__ void __launch_bounds__(1024) sinkf_kernel(
        const float* __restrict__ P1, const float* __restrict__ H1,
        const float* __restrict__ Q1, float* __restrict__ O1, int N1, float la1,
        const float* __restrict__ P2, const float* __restrict__ H2,
        const float* __restrict__ Q2, float* __restrict__ O2, int N2, float la2,
        int hz) {
    extern __shared__ float smem[];
    float4* pts = (float4*)smem;

    int n1b = N1 >> 5;
    int xb = blockIdx.x;
    const float *P, *H, *Q; float *O; int N; float la; int bx;
    if (xb < n1b) { P = P1; H = H1; Q = Q1; O = O1; N = N1; la = la1; bx = xb; }
    else          { P = P2; H = H2; Q = Q2; O = O2; N = N2; la = la2; bx = xb - n1b; }

    int b = blockIdx.y;
    int tid = threadIdx.x;
    const float* Pb = P + (size_t)b * N * 3;
    const float* Hb = H + (size_t)b * N;

    for (int i = tid; i < N; i += 1024) {
        float x = Pb[3 * i], y = Pb[3 * i + 1], z = Pb[3 * i + 2];
        float pn = fmaf(x, x, fmaf(y, y, z * z));
        float hk = hz ? 0.f : Hb[i] * K2F;
        pts[i] = make_float4(x, y, z, fmaf(pn, -K2F, hk));
    }
    __syncthreads();

    int w = tid >> 5, lane = tid & 31;
    int col = (bx << 5) + w;
    const float* Qp = Q + ((size_t)b * N + col) * 3;
    float qx = Qp[0], qy = Qp[1], qz = Qp[2];
    float qn  = fmaf(qx, qx, fmaf(qy, qy, qz * qz));
    float qx2 = 2.f * K2F * qx;
    float qy2 = 2.f * K2F * qy;
    float qz2 = 2.f * K2F * qz;
    float c   = -K2F * qn;

    // pass 1: max over points (lane-strided)
    float m = -1e30f;
#pragma unroll 4
    for (int p = lane; p < N; p += 32) {
        float4 t = pts[p];
        float a = fmaf(t.x, qx2, fmaf(t.y, qy2, fmaf(t.z, qz2, t.w + c)));
        m = fmaxf(m, a);
    }
#pragma unroll
    for (int off = 16; off; off >>= 1)
        m = fmaxf(m, __shfl_xor_sync(0xffffffffu, m, off));

    // pass 2: sum of ex2(a - m)
    float cm = c - m;
    float s = 0.f;
#pragma unroll 4
    for (int p = lane; p < N; p += 32) {
        float4 t = pts[p];
        float a = fmaf(t.x, qx2, fmaf(t.y, qy2, fmaf(t.z, qz2, t.w + cm)));
        s += ex2f(a);
    }
#pragma unroll
    for (int off = 16; off; off >>= 1)
        s += __shfl_xor_sync(0xffffffffu, s, off);

    if (lane == 0)
        O[(size_t)b * N + col] = la - EPSLN2F * (m + lg2f(s));
}

// ---------------------------------------------------------------------------
// Final EMD distance (unchanged).
// ---------------------------------------------------------------------------
__global__ void __launch_bounds__(1024) emddist_kernel(const float* __restrict__ Y,
                                                       const float* __restrict__ G,
                                                       const float* __restrict__ X,
                                                       const float* __restrict__ F,
                                                       int N, int slot) {
    extern __shared__ float smem[];
    float4* pts = (float4*)smem;
    float*  gk  = smem + 4 * N;
    __shared__ float reds[1024];

    int b = blockIdx.y;
    int tid = threadIdx.x;
    const float* Yb = Y + (size_t)b * N * 3;
    const float* Gb = G + (size_t)b * N;

    for (int i = tid; i < N; i += 1024) {
        float x = Yb[3 * i], y = Yb[3 * i + 1], z = Yb[3 * i + 2];
        float pn = fmaf(x, x, fmaf(y, y, z * z));
        pts[i] = make_float4(x, y, z, pn);
        gk[i] = Gb[i] * K2F;
    }
    __syncthreads();

    int col  = (blockIdx.x << 5) + (tid & 31);
    int part = tid >> 5;
    const float* Xp = X + ((size_t)b * N + col) * 3;
    float qx = Xp[0], qy = Xp[1], qz = Xp[2];
    float qn = fmaf(qx, qx, fmaf(qy, qy, qz * qz));
    float fk = F[(size_t)b * N + col] * K2F;

    int chunk = N >> 5;
    int p0 = part * chunk, p1 = p0 + chunk;
    float S = 0.f;
#pragma unroll 4
    for (int p = p0; p < p1; ++p) {
        float4 pt = pts[p];
        float dot = fmaf(pt.x, qx, fmaf(pt.y, qy, pt.z * qz));
        float d   = fmaf(-2.f, dot, pt.w + qn);
        float C   = fmaxf(d, 0.f);
        float arg = fmaf(C, -K2F, fk + gk[p]);
        S = fmaf(ex2f(arg), C, S);
    }
    reds[tid] = S;
    __syncthreads();
    if (tid < 32) {
        float T = 0.f;
#pragma unroll
        for (int k = 0; k < 32; k++) T += reds[k * 32 + tid];
        float v = sqrtf((float)N * T);
#pragma unroll
        for (int off = 16; off; off >>= 1)
            v += __shfl_down_sync(0xffffffffu, v, off);
        if (tid == 0)
            d_emdpart[slot * BATCH * 128 + b * 128 + blockIdx.x] = v;
    }
}

// ---------------------------------------------------------------------------
// Chamfer one direction (unchanged).
// ---------------------------------------------------------------------------
__global__ void __launch_bounds__(256) nnmin_kernel(const float* __restrict__ Q,
                                                    int Nq,
                                                    const float* __restrict__ P,
                                                    int Np, int dir) {
    extern __shared__ float smem[];
    float4* pts = (float4*)smem;
    __shared__ float w1[8], w2[8];

    int b = blockIdx.y;
    int tid = threadIdx.x;
    const float* Pb = P + (size_t)b * Np * 3;
    for (int i = tid; i < Np; i += 256) {
        float x = Pb[3 * i], y = Pb[3 * i + 1], z = Pb[3 * i + 2];
        pts[i] = make_float4(x, y, z, fmaf(x, x, fmaf(y, y, z * z)));
    }
    __syncthreads();

    int qi = blockIdx.x * 256 + tid;
    float vs = 0.f, vq = 0.f;
    if (qi < Nq) {
        const float* Qp = Q + ((size_t)b * Nq + qi) * 3;
        float qx = Qp[0], qy = Qp[1], qz = Qp[2];
        float qn = fmaf(qx, qx, fmaf(qy, qy, qz * qz));
        float best = 1e30f;
#pragma unroll 4
        for (int j = 0; j < Np; ++j) {
            float4 pt = pts[j];
            float dot = fmaf(pt.x, qx, fmaf(pt.y, qy, pt.z * qz));
            float d   = fmaf(-2.f, dot, pt.w + qn);
            d = fmaxf(d, 0.f);
            best = fminf(best, d);
        }
        vq = best;
        vs = sqrtf(best);
    }
#pragma unroll
    for (int off = 16; off; off >>= 1) {
        vs += __shfl_down_sync(0xffffffffu, vs, off);
        vq += __shfl_down_sync(0xffffffffu, vq, off);
    }
    int lane = tid & 31, wid = tid >> 5;
    if (lane == 0) { w1[wid] = vs; w2[wid] = vq; }
    __syncthreads();
    if (tid == 0) {
        float s1 = 0.f, s2 = 0.f;
#pragma unroll
        for (int k = 0; k < 8; k++) { s1 += w1[k]; s2 += w2[k]; }
        int idx = ((dir * BATCH + b) * 16 + blockIdx.x) * 2;
        d_chpart[idx + 0] = s1;
        d_chpart[idx + 1] = s2;
    }
}

// ---------------------------------------------------------------------------
// PU-GAN uniform loss (numerics FROZEN — knife-edge validated).
// ---------------------------------------------------------------------------
template <int GDMODE>
__global__ void __launch_bounds__(256) uniform_kernel(const float* __restrict__ pcd,
                                                      const float* __restrict__ seeds,
                                                      int N, int npoint,
                                                      int nblk) {
    extern __shared__ float smem[];
    float4* cloud = (float4*)smem;
    float*  vpl   = smem + 4 * N;
    __shared__ int lists[8][52];

    float* part = (GDMODE == 0) ? d_upart1 : d_upart2;

    int b = blockIdx.y;
    int tid = threadIdx.x;
    int wid = tid >> 5, lane = tid & 31;
    const float* Pb = pcd + (size_t)b * N * 3;
    for (int i = tid; i < N; i += 256) {
        float x = Pb[3 * i], y = Pb[3 * i + 1], z = Pb[3 * i + 2];
        cloud[i] = make_float4(x, y, z, norm_asc(x, y, z));
        vpl[i] = norm_plain(x, y, z);
    }
    __syncthreads();

    int pidx = (b * nblk + blockIdx.x) * 8 + wid;
    int s = blockIdx.x * 8 + wid;
    if (s >= npoint) {
        if (lane == 0) part[pidx] = 0.f;
        return;
    }

    const float* sp = seeds + ((size_t)b * npoint + s) * 3;
    float sx = sp[0], sy = sp[1], sz = sp[2];
    float sn = norm_asc(sx, sy, sz);
    int* list = lists[wid];
    float tot = 0.f;

    const double PCT[5] = {0.004, 0.006, 0.008, 0.01, 0.012};
#pragma unroll 1
    for (int pi = 0; pi < 5; ++pi) {
        double p = PCT[pi];
        int ns = (int)((float)N * (float)p);
        double r = sqrt(p);
        float r2 = (float)(r * r);
        double expect_d = sqrt(M_PI * p / (double)ns);
        float expect = (float)expect_d;
        float denom = (float)(expect_d + 1e-8);
        float w = (float)((p * 100.0) * (p * 100.0) /
                          (5.0 * (double)BATCH * (double)npoint));

        int cnt = 0;
        for (int base = 0; base < N && cnt < ns; base += 32) {
            int i = base + lane;
            bool in = false;
            if (i < N) {
                float4 pt = cloud[i];
                float dot = dot_asc(sx, sy, sz, pt.x, pt.y, pt.z);
                float d   = sqd_ref(sn, pt.w, dot);
                in = d < r2;
            }
            unsigned bal = __ballot_sync(0xffffffffu, in);
            if (in) {
                int pos = cnt + __popc(bal & ((1u << lane) - 1u));
                if (pos < ns) list[pos] = i;
            }
            cnt += __popc(bal);
            if (cnt > ns) cnt = ns;
        }
        int c = cnt;
        __syncwarp();

        float dsum = 0.f;
        for (int k = lane; k < ns; k += 32) {
            int gi = (k < c) ? list[k] : list[0];
            float4 g = cloud[gi];
            float gn = (GDMODE == 0) ? g.w : vpl[gi];
            float nn = 1e10f;
            for (int j = 0; j < ns; ++j) {
                if (j == k) continue;
                int gj = (j < c) ? list[j] : list[0];
                float4 h = cloud[gj];
                float hn = (GDMODE == 0) ? h.w : vpl[gj];
                float dot = dot_asc(g.x, g.y, g.z, h.x, h.y, h.z);
                float d   = sqd_ref(gn, hn, dot);
                nn = fminf(nn, d);
            }
            dsum += sqrtf(fabsf(__fadd_rn(nn, 1e-8f)));
        }
#pragma unroll
        for (int off = 16; off; off >>= 1)
            dsum += __shfl_down_sync(0xffffffffu, dsum, off);
        if (lane == 0) {
            float mean_d = dsum / (float)ns;
            float df = __fadd_rn(mean_d, -expect);
            tot += (__fmul_rn(df, df) / denom) * w;
        }
        __syncwarp();
    }
    if (lane == 0) part[pidx] = tot;
}

// ---------------------------------------------------------------------------
// finalize (unchanged).
// ---------------------------------------------------------------------------
__global__ void finalize_kernel(float* __restrict__ out) {
    int tid = threadIdx.x;
    const int base = BATCH * NP1 * 3 + BATCH * NP2 * 3;  // 61440
    if (tid < 4) {
        int b = tid;
        float e1 = 0.f, e2 = 0.f;
        for (int k = 0; k < 32; k++)  e1 += d_emdpart[b * 128 + k];
        for (int k = 0; k < 128; k++) e2 += d_emdpart[BATCH * 128 + b * 128 + k];
        out[base + 0 + b] = e1 / (float)NP1;
        out[base + 4 + b] = e2 / (float)NP2;

        const int cnts[4] = {16, 4, 16, 16};
        float cs[4], cq[4];
        for (int dir = 0; dir < 4; dir++) {
            float s = 0.f, q = 0.f;
            for (int k = 0; k < cnts[dir]; k++) {
                int idx = ((dir * BATCH + b) * 16 + k) * 2;
                s += d_chpart[idx + 0];
                q += d_chpart[idx + 1];
            }
            cs[dir] = s; cq[dir] = q;
        }
        out[base + 8 + b]  = 0.5f * (cs[0] / 4096.f + cs[1] / 1024.f);
        out[base + 12 + b] = 0.5f * (cs[2] / 4096.f + cs[3] / 4096.f);
        out[base + 16 + b] = cq[0] / 4096.f + cq[1] / 1024.f;
        out[base + 20 + b] = cq[2] / 4096.f + cq[3] / 4096.f;
    }
    if (tid == 4) {
        float u = 0.f;
        for (int i = 0; i < BATCH * 7 * 8; i++) u += d_upart1[i];
        out[base + 24] = u;
    }
    if (tid == 5) {
        float u = 0.f;
        for (int i = 0; i < BATCH * 26 * 8; i++) u += d_upart2[i];
        out[base + 25] = u;
    }
}

// ---------------------------------------------------------------------------
extern "C" void kernel_launch(void* const* d_in, const int* in_sizes, int n_in,
                              void* d_out, int out_size) {
    const float* o1 = (const float*)d_in[0];
    const float* o2 = (const float*)d_in[1];
    const float* gt = (const float*)d_in[2];
    float* out = (float*)d_out;

    cudaFuncSetAttribute(sinkf_kernel, cudaFuncAttributeMaxDynamicSharedMemorySize, 96 * 1024);
    cudaFuncSetAttribute(emddist_kernel, cudaFuncAttributeMaxDynamicSharedMemorySize, 96 * 1024);
    cudaFuncSetAttribute(nnmin_kernel, cudaFuncAttributeMaxDynamicSharedMemorySize, 72 * 1024);
    cudaFuncSetAttribute(uniform_kernel<0>, cudaFuncAttributeMaxDynamicSharedMemorySize, 96 * 1024);
    cudaFuncSetAttribute(uniform_kernel<1>, cudaFuncAttributeMaxDynamicSharedMemorySize, 96 * 1024);

    // pass-through outputs
    cudaMemcpyAsync(out, o1, (size_t)BATCH * NP1 * 3 * sizeof(float),
                    cudaMemcpyDeviceToDevice, 0);
    cudaMemcpyAsync(out + BATCH * NP1 * 3, o2,
                    (size_t)BATCH * NP2 * 3 * sizeof(float),
                    cudaMemcpyDeviceToDevice, 0);

    // FPS (seeds bit-identical): gt ascFMA; o1/o2 descFMA.
    fps3_kernel<16, 0><<<BATCH, 256>>>(gt, NP1, d_gtfps);
    fps3_kernel<4,  1><<<BATCH, 256>>>(o1, 51, d_seeds1);
    fps3_kernel<16, 1><<<BATCH, 256>>>(o2, 204, d_seeds2);

    // Fused Sinkhorn: each launch advances both chains one half-iteration.
    {
        float la1 = -(float)(0.005 * log((double)NP1));
        float la2 = -(float)(0.005 * log((double)NP2));
        size_t sm = (size_t)NP2 * 16;
        dim3 grid(NP1 / 32 + NP2 / 32, BATCH);  // 160 x 4
        sinkf_kernel<<<grid, 1024, sm>>>(o1, d_f1, d_gtfps, d_g1, NP1, la1,
                                         o2, d_f2, gt,      d_g2, NP2, la2, 1);
        sinkf_kernel<<<grid, 1024, sm>>>(d_gtfps, d_g1, o1, d_f1, NP1, la1,
                                         gt,      d_g2, o2, d_f2, NP2, la2, 0);
        for (int it = 1; it < 10; ++it) {
            sinkf_kernel<<<grid, 1024, sm>>>(o1, d_f1, d_gtfps, d_g1, NP1, la1,
                                             o2, d_f2, gt,      d_g2, NP2, la2, 0);
            sinkf_kernel<<<grid, 1024, sm>>>(d_gtfps, d_g1, o1, d_f1, NP1, la1,
                                             gt,      d_g2, o2, d_f2, NP2, la2, 0);
        }
        emddist_kernel<<<dim3(NP1 / 32, BATCH), 1024, (size_t)NP1 * 20>>>(
            d_gtfps, d_g1, o1, d_f1, NP1, 0);
        emddist_kernel<<<dim3(NP2 / 32, BATCH), 1024, (size_t)NP2 * 20>>>(
            gt, d_g2, o2, d_f2, NP2, 1);
    }

    // Chamfer: dirs 0: gt->o1, 1: o1->gt, 2: gt->o2, 3: o2->gt
    nnmin_kernel<<<dim3(16, BATCH), 256, (size_t)NP1 * 16>>>(gt, NP2, o1, NP1, 0);
    nnmin_kernel<<<dim3(4,  BATCH), 256, (size_t)NP2 * 16>>>(o1, NP1, gt, NP2, 1);
    nnmin_kernel<<<dim3(16, BATCH), 256, (size_t)NP2 * 16>>>(gt, NP2, o2, NP2, 2);
    nnmin_kernel<<<dim3(16, BATCH), 256, (size_t)NP2 * 16>>>(o2, NP2, gt, NP2, 3);

    // Uniform losses: o1 matched gd; o2 mismatched gd.
    uniform_kernel<0><<<dim3(7,  BATCH), 256, (size_t)NP1 * 20>>>(o1, d_seeds1, NP1, 51, 7);
    uniform_kernel<1><<<dim3(26, BATCH), 256, (size_t)NP2 * 20>>>(o2, d_seeds2, NP2, 204, 26);

    finalize_kernel<<<1, 32>>>(out);
}

// round 15
// speedup vs baseline: 1.3059x; 1.3059x over previous
#include <cuda_runtime.h>
#include <math.h>
#include <stdint.h>

// Shapes: output1 (4,1024,3), output2 (4,4096,3), gt (4,4096,3)
#define BATCH 4
#define NP1 1024
#define NP2 4096
// log2(e)/eps, eps = 0.005
#define K2F 288.5390081777927f
// eps*ln(2)
#define EPSLN2F 0.0034657359027997265f

// scratch (__device__ globals). Every buffer fully written before read
// within one call — no cross-call state, no atomics, no stream/event objects.
__device__ float d_gtfps[BATCH * NP1 * 3];
__device__ float d_seeds1[BATCH * 51 * 3];
__device__ float d_seeds2[BATCH * 204 * 3];
__device__ float d_f1[BATCH * NP1];
__device__ float d_g1[BATCH * NP1];
__device__ float d_f2[BATCH * NP2];
__device__ float d_g2[BATCH * NP2];
__device__ float d_emdpart[2 * BATCH * 128];
__device__ float d_chpart[4 * BATCH * 16 * 2];
__device__ float d_upart1[BATCH * 7 * 8];
__device__ float d_upart2[BATCH * 26 * 8];

__device__ __forceinline__ float ex2f(float x) {
    float y; asm("ex2.approx.f32 %0, %1;" : "=f"(y) : "f"(x)); return y;
}
__device__ __forceinline__ float lg2f(float x) {
    float y; asm("lg2.approx.f32 %0, %1;" : "=f"(y) : "f"(x)); return y;
}

// Lowering helpers (validated — uniform loss is knife-edge, frozen).
__device__ __forceinline__ float norm_plain(float x, float y, float z) {
    return __fadd_rn(__fadd_rn(__fmul_rn(x, x), __fmul_rn(y, y)), __fmul_rn(z, z));
}
__device__ __forceinline__ float norm_asc(float x, float y, float z) {
    return fmaf(z, z, fmaf(y, y, __fmul_rn(x, x)));
}
__device__ __forceinline__ float dot_asc(float x, float y, float z,
                                         float qx, float qy, float qz) {
    return fmaf(z, qz, fmaf(y, qy, __fmul_rn(x, qx)));
}
__device__ __forceinline__ float sqd_ref(float an, float bn, float dot) {
    float d = fmaf(-2.f, dot, __fadd_rn(an, bn));
    return fmaxf(d, 0.f);
}

// ---------------------------------------------------------------------------
// FPS v3 (validated in R14: seeds bit-identical; big win — unchanged).
// ---------------------------------------------------------------------------
template <int PP, int FORM>
__global__ void __launch_bounds__(256) fps3_kernel(const float* __restrict__ pcd,
                                                   int npoint,
                                                   float* __restrict__ outc) {
    const int NT = 256;
    const int N = PP * NT;
    int b = blockIdx.x;
    int tid = threadIdx.x;
    int lane = tid & 31, wid = tid >> 5;
    const float* Pb = pcd + (size_t)b * N * 3;

    float px[PP], py[PP], pz[PP], dd[PP];
#pragma unroll
    for (int k = 0; k < PP; k++) {
        int idx = tid + k * NT;
        px[k] = Pb[3 * idx]; py[k] = Pb[3 * idx + 1]; pz[k] = Pb[3 * idx + 2];
        dd[k] = 1e10f;
    }

    __shared__ unsigned long long wk[2][8];
    int far = 0;

    for (int it = 0; it < npoint; ++it) {
        float cx = Pb[3 * far], cy = Pb[3 * far + 1], cz = Pb[3 * far + 2];
        if (tid == 0) {
            float* o = outc + ((size_t)b * npoint + it) * 3;
            o[0] = cx; o[1] = cy; o[2] = cz;
        }
        float bv = -1.f; int bi = N;
#pragma unroll
        for (int k = 0; k < PP; k++) {
            float dx = __fadd_rn(px[k], -cx);
            float dy = __fadd_rn(py[k], -cy);
            float dz = __fadd_rn(pz[k], -cz);
            float d;
            if (FORM == 0)
                d = fmaf(dz, dz, fmaf(dy, dy, __fmul_rn(dx, dx)));
            else
                d = fmaf(dx, dx, fmaf(dy, dy, __fmul_rn(dz, dz)));
            float nd = fminf(dd[k], d);
            dd[k] = nd;
            int idx = tid + k * NT;
            if (nd > bv || (nd == bv && idx < bi)) { bv = nd; bi = idx; }
        }
        unsigned ud = __float_as_uint(bv);
        unsigned um = __reduce_max_sync(0xffffffffu, ud);
        unsigned cand = (ud == um) ? (unsigned)bi : 0x7fffffffu;
        unsigned bw = __reduce_min_sync(0xffffffffu, cand);
        if (lane == 0)
            wk[it & 1][wid] = ((unsigned long long)um << 32) |
                              (unsigned)(N - (int)bw);
        __syncthreads();
        unsigned long long m = wk[it & 1][0];
#pragma unroll
        for (int w = 1; w < 8; w++) {
            unsigned long long o = wk[it & 1][w];
            m = o > m ? o : m;
        }
        far = N - (int)(m & 0xFFFFFFFFull);
    }
}

// ---------------------------------------------------------------------------
// Fused Sinkhorn half-iteration v3: broadcast smem reads + single-pass LSE.
//  - 128 columns per block (col = tid&127), 8 point-splits (s = tid>>7):
//    warp lanes share p -> every LDS is a broadcast (no crossbar conflicts).
//  - no max pass: a = (H - C)*log2e/eps; row max >= ~-13 (nearest neighbor
//    in unit cube), so sum of ex2(a) never fully underflows; terms below
//    2^-126 vanish but are below fp32 addition resolution anyway.
//  - deterministic 8-way fixed-order reduction.
// Blocks x < N1/128 serve chain 1 (emd1), the rest chain 2 (emd2).
// ---------------------------------------------------------------------------
__global__ void __launch_bounds__(1024) sinkf_kernel(
        const float* __restrict__ P1, const float* __restrict__ H1,
        const float* __restrict__ Q1, float* __restrict__ O1, int N1, float la1,
        const float* __restrict__ P2, const float* __restrict__ H2,
        const float* __restrict__ Q2, float* __restrict__ O2, int N2, float la2,
        int hz) {
    extern __shared__ float smem[];

    int n1b = N1 >> 7;
    int xb = blockIdx.x;
    const float *P, *H, *Q; float *O; int N; float la; int bx;
    if (xb < n1b) { P = P1; H = H1; Q = Q1; O = O1; N = N1; la = la1; bx = xb; }
    else          { P = P2; H = H2; Q = Q2; O = O2; N = N2; la = la2; bx = xb - n1b; }

    float4* pts = (float4*)smem;
    float*  red = smem + 4 * N;     // 8 * 128 floats

    int b = blockIdx.y;
    int tid = threadIdx.x;
    const float* Pb = P + (size_t)b * N * 3;
    const float* Hb = H + (size_t)b * N;

    for (int i = tid; i < N; i += 1024) {
        float x = Pb[3 * i], y = Pb[3 * i + 1], z = Pb[3 * i + 2];
        float pn = fmaf(x, x, fmaf(y, y, z * z));
        float hk = hz ? 0.f : Hb[i] * K2F;
        pts[i] = make_float4(x, y, z, fmaf(pn, -K2F, hk));
    }
    __syncthreads();

    int c7  = tid & 127;
    int s   = tid >> 7;             // 0..7
    int col = (bx << 7) + c7;
    const float* Qp = Q + ((size_t)b * N + col) * 3;
    float qx = Qp[0], qy = Qp[1], qz = Qp[2];
    float qn  = fmaf(qx, qx, fmaf(qy, qy, qz * qz));
    float qx2 = 2.f * K2F * qx;
    float qy2 = 2.f * K2F * qy;
    float qz2 = 2.f * K2F * qz;
    float c   = -K2F * qn;

    int chunk = N >> 3;
    int p0 = s * chunk, p1 = p0 + chunk;
    float sum = 0.f;
#pragma unroll 4
    for (int p = p0; p < p1; ++p) {
        float4 t = pts[p];
        float a = fmaf(t.x, qx2, fmaf(t.y, qy2, fmaf(t.z, qz2, t.w + c)));
        sum += ex2f(a);
    }
    red[s * 128 + c7] = sum;
    __syncthreads();
    if (tid < 128) {
        float S = red[tid];
#pragma unroll
        for (int k = 1; k < 8; k++) S += red[k * 128 + tid];
        O[(size_t)b * N + (bx << 7) + tid] = la - EPSLN2F * lg2f(S);
    }
}

// ---------------------------------------------------------------------------
// Final EMD distance (unchanged).
// ---------------------------------------------------------------------------
__global__ void __launch_bounds__(1024) emddist_kernel(const float* __restrict__ Y,
                                                       const float* __restrict__ G,
                                                       const float* __restrict__ X,
                                                       const float* __restrict__ F,
                                                       int N, int slot) {
    extern __shared__ float smem[];
    float4* pts = (float4*)smem;
    float*  gk  = smem + 4 * N;
    __shared__ float reds[1024];

    int b = blockIdx.y;
    int tid = threadIdx.x;
    const float* Yb = Y + (size_t)b * N * 3;
    const float* Gb = G + (size_t)b * N;

    for (int i = tid; i < N; i += 1024) {
        float x = Yb[3 * i], y = Yb[3 * i + 1], z = Yb[3 * i + 2];
        float pn = fmaf(x, x, fmaf(y, y, z * z));
        pts[i] = make_float4(x, y, z, pn);
        gk[i] = Gb[i] * K2F;
    }
    __syncthreads();

    int col  = (blockIdx.x << 5) + (tid & 31);
    int part = tid >> 5;
    const float* Xp = X + ((size_t)b * N + col) * 3;
    float qx = Xp[0], qy = Xp[1], qz = Xp[2];
    float qn = fmaf(qx, qx, fmaf(qy, qy, qz * qz));
    float fk = F[(size_t)b * N + col] * K2F;

    int chunk = N >> 5;
    int p0 = part * chunk, p1 = p0 + chunk;
    float S = 0.f;
#pragma unroll 4
    for (int p = p0; p < p1; ++p) {
        float4 pt = pts[p];
        float dot = fmaf(pt.x, qx, fmaf(pt.y, qy, pt.z * qz));
        float d   = fmaf(-2.f, dot, pt.w + qn);
        float C   = fmaxf(d, 0.f);
        float arg = fmaf(C, -K2F, fk + gk[p]);
        S = fmaf(ex2f(arg), C, S);
    }
    reds[tid] = S;
    __syncthreads();
    if (tid < 32) {
        float T = 0.f;
#pragma unroll
        for (int k = 0; k < 32; k++) T += reds[k * 32 + tid];
        float v = sqrtf((float)N * T);
#pragma unroll
        for (int off = 16; off; off >>= 1)
            v += __shfl_down_sync(0xffffffffu, v, off);
        if (tid == 0)
            d_emdpart[slot * BATCH * 128 + b * 128 + blockIdx.x] = v;
    }
}

// ---------------------------------------------------------------------------
// Fused Chamfer: all 4 directions in one launch.
//  xb 0..15: gt->o1 | 16..19: o1->gt | 20..35: gt->o2 | 36..51: o2->gt
// ---------------------------------------------------------------------------
__global__ void __launch_bounds__(256) nnminf_kernel(const float* __restrict__ o1,
                                                     const float* __restrict__ o2,
                                                     const float* __restrict__ gt) {
    extern __shared__ float smem[];
    float4* pts = (float4*)smem;
    __shared__ float w1[8], w2[8];

    int xb = blockIdx.x;
    const float *Q, *P; int Nq, Np, dir, bx;
    if (xb < 16)      { dir = 0; bx = xb;      Q = gt; Nq = NP2; P = o1; Np = NP1; }
    else if (xb < 20) { dir = 1; bx = xb - 16; Q = o1; Nq = NP1; P = gt; Np = NP2; }
    else if (xb < 36) { dir = 2; bx = xb - 20; Q = gt; Nq = NP2; P = o2; Np = NP2; }
    else              { dir = 3; bx = xb - 36; Q = o2; Nq = NP2; P = gt; Np = NP2; }

    int b = blockIdx.y;
    int tid = threadIdx.x;
    const float* Pb = P + (size_t)b * Np * 3;
    for (int i = tid; i < Np; i += 256) {
        float x = Pb[3 * i], y = Pb[3 * i + 1], z = Pb[3 * i + 2];
        pts[i] = make_float4(x, y, z, fmaf(x, x, fmaf(y, y, z * z)));
    }
    __syncthreads();

    int qi = bx * 256 + tid;
    float vs = 0.f, vq = 0.f;
    if (qi < Nq) {
        const float* Qp = Q + ((size_t)b * Nq + qi) * 3;
        float qx = Qp[0], qy = Qp[1], qz = Qp[2];
        float qn = fmaf(qx, qx, fmaf(qy, qy, qz * qz));
        float best = 1e30f;
#pragma unroll 4
        for (int j = 0; j < Np; ++j) {
            float4 pt = pts[j];
            float dot = fmaf(pt.x, qx, fmaf(pt.y, qy, pt.z * qz));
            float d   = fmaf(-2.f, dot, pt.w + qn);
            d = fmaxf(d, 0.f);
            best = fminf(best, d);
        }
        vq = best;
        vs = sqrtf(best);
    }
#pragma unroll
    for (int off = 16; off; off >>= 1) {
        vs += __shfl_down_sync(0xffffffffu, vs, off);
        vq += __shfl_down_sync(0xffffffffu, vq, off);
    }
    int lane = tid & 31, wid = tid >> 5;
    if (lane == 0) { w1[wid] = vs; w2[wid] = vq; }
    __syncthreads();
    if (tid == 0) {
        float s1 = 0.f, s2 = 0.f;
#pragma unroll
        for (int k = 0; k < 8; k++) { s1 += w1[k]; s2 += w2[k]; }
        int idx = ((dir * BATCH + b) * 16 + bx) * 2;
        d_chpart[idx + 0] = s1;
        d_chpart[idx + 1] = s2;
    }
}

// ---------------------------------------------------------------------------
// PU-GAN uniform loss (numerics FROZEN — knife-edge validated).
// ---------------------------------------------------------------------------
template <int GDMODE>
__global__ void __launch_bounds__(256) uniform_kernel(const float* __restrict__ pcd,
                                                      const float* __restrict__ seeds,
                                                      int N, int npoint,
                                                      int nblk) {
    extern __shared__ float smem[];
    float4* cloud = (float4*)smem;
    float*  vpl   = smem + 4 * N;
    __shared__ int lists[8][52];

    float* part = (GDMODE == 0) ? d_upart1 : d_upart2;

    int b = blockIdx.y;
    int tid = threadIdx.x;
    int wid = tid >> 5, lane = tid & 31;
    const float* Pb = pcd + (size_t)b * N * 3;
    for (int i = tid; i < N; i += 256) {
        float x = Pb[3 * i], y = Pb[3 * i + 1], z = Pb[3 * i + 2];
        cloud[i] = make_float4(x, y, z, norm_asc(x, y, z));
        vpl[i] = norm_plain(x, y, z);
    }
    __syncthreads();

    int pidx = (b * nblk + blockIdx.x) * 8 + wid;
    int s = blockIdx.x * 8 + wid;
    if (s >= npoint) {
        if (lane == 0) part[pidx] = 0.f;
        return;
    }

    const float* sp = seeds + ((size_t)b * npoint + s) * 3;
    float sx = sp[0], sy = sp[1], sz = sp[2];
    float sn = norm_asc(sx, sy, sz);
    int* list = lists[wid];
    float tot = 0.f;

    const double PCT[5] = {0.004, 0.006, 0.008, 0.01, 0.012};
#pragma unroll 1
    for (int pi = 0; pi < 5; ++pi) {
        double p = PCT[pi];
        int ns = (int)((float)N * (float)p);
        double r = sqrt(p);
        float r2 = (float)(r * r);
        double expect_d = sqrt(M_PI * p / (double)ns);
        float expect = (float)expect_d;
        float denom = (float)(expect_d + 1e-8);
        float w = (float)((p * 100.0) * (p * 100.0) /
                          (5.0 * (double)BATCH * (double)npoint));

        int cnt = 0;
        for (int base = 0; base < N && cnt < ns; base += 32) {
            int i = base + lane;
            bool in = false;
            if (i < N) {
                float4 pt = cloud[i];
                float dot = dot_asc(sx, sy, sz, pt.x, pt.y, pt.z);
                float d   = sqd_ref(sn, pt.w, dot);
                in = d < r2;
            }
            unsigned bal = __ballot_sync(0xffffffffu, in);
            if (in) {
                int pos = cnt + __popc(bal & ((1u << lane) - 1u));
                if (pos < ns) list[pos] = i;
            }
            cnt += __popc(bal);
            if (cnt > ns) cnt = ns;
        }
        int c = cnt;
        __syncwarp();

        float dsum = 0.f;
        for (int k = lane; k < ns; k += 32) {
            int gi = (k < c) ? list[k] : list[0];
            float4 g = cloud[gi];
            float gn = (GDMODE == 0) ? g.w : vpl[gi];
            float nn = 1e10f;
            for (int j = 0; j < ns; ++j) {
                if (j == k) continue;
                int gj = (j < c) ? list[j] : list[0];
                float4 h = cloud[gj];
                float hn = (GDMODE == 0) ? h.w : vpl[gj];
                float dot = dot_asc(g.x, g.y, g.z, h.x, h.y, h.z);
                float d   = sqd_ref(gn, hn, dot);
                nn = fminf(nn, d);
            }
            dsum += sqrtf(fabsf(__fadd_rn(nn, 1e-8f)));
        }
#pragma unroll
        for (int off = 16; off; off >>= 1)
            dsum += __shfl_down_sync(0xffffffffu, dsum, off);
        if (lane == 0) {
            float mean_d = dsum / (float)ns;
            float df = __fadd_rn(mean_d, -expect);
            tot += (__fmul_rn(df, df) / denom) * w;
        }
        __syncwarp();
    }
    if (lane == 0) part[pidx] = tot;
}

// ---------------------------------------------------------------------------
// finalize (unchanged).
// ---------------------------------------------------------------------------
__global__ void finalize_kernel(float* __restrict__ out) {
    int tid = threadIdx.x;
    const int base = BATCH * NP1 * 3 + BATCH * NP2 * 3;  // 61440
    if (tid < 4) {
        int b = tid;
        float e1 = 0.f, e2 = 0.f;
        for (int k = 0; k < 32; k++)  e1 += d_emdpart[b * 128 + k];
        for (int k = 0; k < 128; k++) e2 += d_emdpart[BATCH * 128 + b * 128 + k];
        out[base + 0 + b] = e1 / (float)NP1;
        out[base + 4 + b] = e2 / (float)NP2;

        const int cnts[4] = {16, 4, 16, 16};
        float cs[4], cq[4];
        for (int dir = 0; dir < 4; dir++) {
            float s = 0.f, q = 0.f;
            for (int k = 0; k < cnts[dir]; k++) {
                int idx = ((dir * BATCH + b) * 16 + k) * 2;
                s += d_chpart[idx + 0];
                q += d_chpart[idx + 1];
            }
            cs[dir] = s; cq[dir] = q;
        }
        out[base + 8 + b]  = 0.5f * (cs[0] / 4096.f + cs[1] / 1024.f);
        out[base + 12 + b] = 0.5f * (cs[2] / 4096.f + cs[3] / 4096.f);
        out[base + 16 + b] = cq[0] / 4096.f + cq[1] / 1024.f;
        out[base + 20 + b] = cq[2] / 4096.f + cq[3] / 4096.f;
    }
    if (tid == 4) {
        float u = 0.f;
        for (int i = 0; i < BATCH * 7 * 8; i++) u += d_upart1[i];
        out[base + 24] = u;
    }
    if (tid == 5) {
        float u = 0.f;
        for (int i = 0; i < BATCH * 26 * 8; i++) u += d_upart2[i];
        out[base + 25] = u;
    }
}

// ---------------------------------------------------------------------------
extern "C" void kernel_launch(void* const* d_in, const int* in_sizes, int n_in,
                              void* d_out, int out_size) {
    const float* o1 = (const float*)d_in[0];
    const float* o2 = (const float*)d_in[1];
    const float* gt = (const float*)d_in[2];
    float* out = (float*)d_out;

    cudaFuncSetAttribute(sinkf_kernel, cudaFuncAttributeMaxDynamicSharedMemorySize, 96 * 1024);
    cudaFuncSetAttribute(emddist_kernel, cudaFuncAttributeMaxDynamicSharedMemorySize, 96 * 1024);
    cudaFuncSetAttribute(nnminf_kernel, cudaFuncAttributeMaxDynamicSharedMemorySize, 72 * 1024);
    cudaFuncSetAttribute(uniform_kernel<0>, cudaFuncAttributeMaxDynamicSharedMemorySize, 96 * 1024);
    cudaFuncSetAttribute(uniform_kernel<1>, cudaFuncAttributeMaxDynamicSharedMemorySize, 96 * 1024);

    // pass-through outputs
    cudaMemcpyAsync(out, o1, (size_t)BATCH * NP1 * 3 * sizeof(float),
                    cudaMemcpyDeviceToDevice, 0);
    cudaMemcpyAsync(out + BATCH * NP1 * 3, o2,
                    (size_t)BATCH * NP2 * 3 * sizeof(float),
                    cudaMemcpyDeviceToDevice, 0);

    // FPS (seeds bit-identical): gt ascFMA; o1/o2 descFMA.
    fps3_kernel<16, 0><<<BATCH, 256>>>(gt, NP1, d_gtfps);
    fps3_kernel<4,  1><<<BATCH, 256>>>(o1, 51, d_seeds1);
    fps3_kernel<16, 1><<<BATCH, 256>>>(o2, 204, d_seeds2);

    // Fused Sinkhorn: each launch advances both chains one half-iteration.
    {
        float la1 = -(float)(0.005 * log((double)NP1));
        float la2 = -(float)(0.005 * log((double)NP2));
        size_t sm = (size_t)NP2 * 16 + 8 * 128 * 4;   // pts + red
        dim3 grid(NP1 / 128 + NP2 / 128, BATCH);      // 40 x 4
        sinkf_kernel<<<grid, 1024, sm>>>(o1, d_f1, d_gtfps, d_g1, NP1, la1,
                                         o2, d_f2, gt,      d_g2, NP2, la2, 1);
        sinkf_kernel<<<grid, 1024, sm>>>(d_gtfps, d_g1, o1, d_f1, NP1, la1,
                                         gt,      d_g2, o2, d_f2, NP2, la2, 0);
        for (int it = 1; it < 10; ++it) {
            sinkf_kernel<<<grid, 1024, sm>>>(o1, d_f1, d_gtfps, d_g1, NP1, la1,
                                             o2, d_f2, gt,      d_g2, NP2, la2, 0);
            sinkf_kernel<<<grid, 1024, sm>>>(d_gtfps, d_g1, o1, d_f1, NP1, la1,
                                             gt,      d_g2, o2, d_f2, NP2, la2, 0);
        }
        emddist_kernel<<<dim3(NP1 / 32, BATCH), 1024, (size_t)NP1 * 20>>>(
            d_gtfps, d_g1, o1, d_f1, NP1, 0);
        emddist_kernel<<<dim3(NP2 / 32, BATCH), 1024, (size_t)NP2 * 20>>>(
            gt, d_g2, o2, d_f2, NP2, 1);
    }

    // Fused Chamfer (4 directions, one launch).
    nnminf_kernel<<<dim3(52, BATCH), 256, (size_t)NP2 * 16>>>(o1, o2, gt);

    // Uniform losses: o1 matched gd; o2 mismatched gd.
    uniform_kernel<0><<<dim3(7,  BATCH), 256, (size_t)NP1 * 20>>>(o1, d_seeds1, NP1, 51, 7);
    uniform_kernel<1><<<dim3(26, BATCH), 256, (size_t)NP2 * 20>>>(o2, d_seeds2, NP2, 204, 26);

    finalize_kernel<<<1, 32>>>(out);
}

// round 17
// speedup vs baseline: 1.6434x; 1.2585x over previous
#include <cuda_runtime.h>
#include <math.h>
#include <stdint.h>

// Shapes: output1 (4,1024,3), output2 (4,4096,3), gt (4,4096,3)
#define BATCH 4
#define NP1 1024
#define NP2 4096
// log2(e)/eps, eps = 0.005
#define K2F 288.5390081777927f
// eps*ln(2)
#define EPSLN2F 0.0034657359027997265f

// scratch (__device__ globals). Every buffer fully written before read
// within one call — no cross-call state, no atomics, no stream/event objects.
__device__ float d_gtfps[BATCH * NP1 * 3];
__device__ float d_seeds1[BATCH * 51 * 3];
__device__ float d_seeds2[BATCH * 204 * 3];
__device__ float d_f1[BATCH * NP1];
__device__ float d_g1[BATCH * NP1];
__device__ float d_f2[BATCH * NP2];
__device__ float d_g2[BATCH * NP2];
__device__ float d_emdpart[2 * BATCH * 128];
__device__ float d_chpart[4 * BATCH * 16 * 2];
__device__ float d_upart1[BATCH * 7 * 8];
__device__ float d_upart2[BATCH * 26 * 8];

__device__ __forceinline__ float ex2f(float x) {
    float y; asm("ex2.approx.f32 %0, %1;" : "=f"(y) : "f"(x)); return y;
}
__device__ __forceinline__ float lg2f(float x) {
    float y; asm("lg2.approx.f32 %0, %1;" : "=f"(y) : "f"(x)); return y;
}

// Lowering helpers (validated — uniform loss is knife-edge, frozen).
__device__ __forceinline__ float norm_plain(float x, float y, float z) {
    return __fadd_rn(__fadd_rn(__fmul_rn(x, x), __fmul_rn(y, y)), __fmul_rn(z, z));
}
__device__ __forceinline__ float norm_asc(float x, float y, float z) {
    return fmaf(z, z, fmaf(y, y, __fmul_rn(x, x)));
}
__device__ __forceinline__ float dot_asc(float x, float y, float z,
                                         float qx, float qy, float qz) {
    return fmaf(z, qz, fmaf(y, qy, __fmul_rn(x, qx)));
}
__device__ __forceinline__ float sqd_ref(float an, float bn, float dot) {
    float d = fmaf(-2.f, dot, __fadd_rn(an, bn));
    return fmaxf(d, 0.f);
}

// ---------------------------------------------------------------------------
// FPS v3 (R15 exact — seeds bit-identical, proven).
// ---------------------------------------------------------------------------
template <int PP, int FORM>
__global__ void __launch_bounds__(256) fps3_kernel(const float* __restrict__ pcd,
                                                   int npoint,
                                                   float* __restrict__ outc) {
    const int NT = 256;
    const int N = PP * NT;
    int b = blockIdx.x;
    int tid = threadIdx.x;
    int lane = tid & 31, wid = tid >> 5;
    const float* Pb = pcd + (size_t)b * N * 3;

    float px[PP], py[PP], pz[PP], dd[PP];
#pragma unroll
    for (int k = 0; k < PP; k++) {
        int idx = tid + k * NT;
        px[k] = Pb[3 * idx]; py[k] = Pb[3 * idx + 1]; pz[k] = Pb[3 * idx + 2];
        dd[k] = 1e10f;
    }

    __shared__ unsigned long long wk[2][8];
    int far = 0;

    for (int it = 0; it < npoint; ++it) {
        float cx = Pb[3 * far], cy = Pb[3 * far + 1], cz = Pb[3 * far + 2];
        if (tid == 0) {
            float* o = outc + ((size_t)b * npoint + it) * 3;
            o[0] = cx; o[1] = cy; o[2] = cz;
        }
        float bv = -1.f; int bi = N;
#pragma unroll
        for (int k = 0; k < PP; k++) {
            float dx = __fadd_rn(px[k], -cx);
            float dy = __fadd_rn(py[k], -cy);
            float dz = __fadd_rn(pz[k], -cz);
            float d;
            if (FORM == 0)
                d = fmaf(dz, dz, fmaf(dy, dy, __fmul_rn(dx, dx)));
            else
                d = fmaf(dx, dx, fmaf(dy, dy, __fmul_rn(dz, dz)));
            float nd = fminf(dd[k], d);
            dd[k] = nd;
            int idx = tid + k * NT;
            if (nd > bv || (nd == bv && idx < bi)) { bv = nd; bi = idx; }
        }
        unsigned ud = __float_as_uint(bv);
        unsigned um = __reduce_max_sync(0xffffffffu, ud);
        unsigned cand = (ud == um) ? (unsigned)bi : 0x7fffffffu;
        unsigned bw = __reduce_min_sync(0xffffffffu, cand);
        if (lane == 0)
            wk[it & 1][wid] = ((unsigned long long)um << 32) |
                              (unsigned)(N - (int)bw);
        __syncthreads();
        unsigned long long m = wk[it & 1][0];
#pragma unroll
        for (int w = 1; w < 8; w++) {
            unsigned long long o = wk[it & 1][w];
            m = o > m ? o : m;
        }
        far = N - (int)(m & 0xFFFFFFFFull);
    }
}

// ---------------------------------------------------------------------------
// Sinkhorn: R15 structure exactly, with the ONLY change being a compile-time
// trip-count inner summation (sequential accumulation chain preserved =>
// bitwise-identical results to R15).
// ---------------------------------------------------------------------------
template <int N>
__device__ __forceinline__ float sink_col_sum(const float4* __restrict__ pts,
                                              float qx2, float qy2, float qz2,
                                              float c, int s) {
    const int chunk = N >> 3;
    const float4* pp = pts + s * chunk;
    float sum = 0.f;
#pragma unroll 16
    for (int k = 0; k < chunk; ++k) {
        float4 t = pp[k];
        float a = fmaf(t.x, qx2, fmaf(t.y, qy2, fmaf(t.z, qz2, t.w + c)));
        sum += ex2f(a);
    }
    return sum;
}

__global__ void __launch_bounds__(1024) sinkf_kernel(
        const float* __restrict__ P1, const float* __restrict__ H1,
        const float* __restrict__ Q1, float* __restrict__ O1, int N1, float la1,
        const float* __restrict__ P2, const float* __restrict__ H2,
        const float* __restrict__ Q2, float* __restrict__ O2, int N2, float la2,
        int hz) {
    extern __shared__ float smem[];

    int n1b = N1 >> 7;
    int xb = blockIdx.x;
    const float *P, *H, *Q; float *O; int N; float la; int bx;
    if (xb < n1b) { P = P1; H = H1; Q = Q1; O = O1; N = N1; la = la1; bx = xb; }
    else          { P = P2; H = H2; Q = Q2; O = O2; N = N2; la = la2; bx = xb - n1b; }

    float4* pts = (float4*)smem;
    float*  red = smem + 4 * N;     // 8 * 128 floats

    int b = blockIdx.y;
    int tid = threadIdx.x;
    const float* Pb = P + (size_t)b * N * 3;
    const float* Hb = H + (size_t)b * N;

    for (int i = tid; i < N; i += 1024) {
        float x = Pb[3 * i], y = Pb[3 * i + 1], z = Pb[3 * i + 2];
        float pn = fmaf(x, x, fmaf(y, y, z * z));
        float hk = hz ? 0.f : Hb[i] * K2F;
        pts[i] = make_float4(x, y, z, fmaf(pn, -K2F, hk));
    }
    __syncthreads();

    int c7  = tid & 127;
    int s   = tid >> 7;             // 0..7
    int col = (bx << 7) + c7;
    const float* Qp = Q + ((size_t)b * N + col) * 3;
    float qx = Qp[0], qy = Qp[1], qz = Qp[2];
    float qn  = fmaf(qx, qx, fmaf(qy, qy, qz * qz));
    float qx2 = 2.f * K2F * qx;
    float qy2 = 2.f * K2F * qy;
    float qz2 = 2.f * K2F * qz;
    float c   = -K2F * qn;

    float sum = (N == NP1)
        ? sink_col_sum<NP1>(pts, qx2, qy2, qz2, c, s)
        : sink_col_sum<NP2>(pts, qx2, qy2, qz2, c, s);
    red[s * 128 + c7] = sum;
    __syncthreads();
    if (tid < 128) {
        float S = red[tid];
#pragma unroll
        for (int k = 1; k < 8; k++) S += red[k * 128 + tid];
        O[(size_t)b * N + (bx << 7) + tid] = la - EPSLN2F * lg2f(S);
    }
}

// ---------------------------------------------------------------------------
// Final EMD distance (R15 exact).
// ---------------------------------------------------------------------------
__global__ void __launch_bounds__(1024) emddist_kernel(const float* __restrict__ Y,
                                                       const float* __restrict__ G,
                                                       const float* __restrict__ X,
                                                       const float* __restrict__ F,
                                                       int N, int slot) {
    extern __shared__ float smem[];
    float4* pts = (float4*)smem;
    float*  gk  = smem + 4 * N;
    __shared__ float reds[1024];

    int b = blockIdx.y;
    int tid = threadIdx.x;
    const float* Yb = Y + (size_t)b * N * 3;
    const float* Gb = G + (size_t)b * N;

    for (int i = tid; i < N; i += 1024) {
        float x = Yb[3 * i], y = Yb[3 * i + 1], z = Yb[3 * i + 2];
        float pn = fmaf(x, x, fmaf(y, y, z * z));
        pts[i] = make_float4(x, y, z, pn);
        gk[i] = Gb[i] * K2F;
    }
    __syncthreads();

    int col  = (blockIdx.x << 5) + (tid & 31);
    int part = tid >> 5;
    const float* Xp = X + ((size_t)b * N + col) * 3;
    float qx = Xp[0], qy = Xp[1], qz = Xp[2];
    float qn = fmaf(qx, qx, fmaf(qy, qy, qz * qz));
    float fk = F[(size_t)b * N + col] * K2F;

    int chunk = N >> 5;
    int p0 = part * chunk, p1 = p0 + chunk;
    float S = 0.f;
#pragma unroll 4
    for (int p = p0; p < p1; ++p) {
        float4 pt = pts[p];
        float dot = fmaf(pt.x, qx, fmaf(pt.y, qy, pt.z * qz));
        float d   = fmaf(-2.f, dot, pt.w + qn);
        float C   = fmaxf(d, 0.f);
        float arg = fmaf(C, -K2F, fk + gk[p]);
        S = fmaf(ex2f(arg), C, S);
    }
    reds[tid] = S;
    __syncthreads();
    if (tid < 32) {
        float T = 0.f;
#pragma unroll
        for (int k = 0; k < 32; k++) T += reds[k * 32 + tid];
        float v = sqrtf((float)N * T);
#pragma unroll
        for (int off = 16; off; off >>= 1)
            v += __shfl_down_sync(0xffffffffu, v, off);
        if (tid == 0)
            d_emdpart[slot * BATCH * 128 + b * 128 + blockIdx.x] = v;
    }
}

// ---------------------------------------------------------------------------
// Fused Chamfer: all 4 directions in one launch (R15 exact).
// ---------------------------------------------------------------------------
__global__ void __launch_bounds__(256) nnminf_kernel(const float* __restrict__ o1,
                                                     const float* __restrict__ o2,
                                                     const float* __restrict__ gt) {
    extern __shared__ float smem[];
    float4* pts = (float4*)smem;
    __shared__ float w1[8], w2[8];

    int xb = blockIdx.x;
    const float *Q, *P; int Nq, Np, dir, bx;
    if (xb < 16)      { dir = 0; bx = xb;      Q = gt; Nq = NP2; P = o1; Np = NP1; }
    else if (xb < 20) { dir = 1; bx = xb - 16; Q = o1; Nq = NP1; P = gt; Np = NP2; }
    else if (xb < 36) { dir = 2; bx = xb - 20; Q = gt; Nq = NP2; P = o2; Np = NP2; }
    else              { dir = 3; bx = xb - 36; Q = o2; Nq = NP2; P = gt; Np = NP2; }

    int b = blockIdx.y;
    int tid = threadIdx.x;
    const float* Pb = P + (size_t)b * Np * 3;
    for (int i = tid; i < Np; i += 256) {
        float x = Pb[3 * i], y = Pb[3 * i + 1], z = Pb[3 * i + 2];
        pts[i] = make_float4(x, y, z, fmaf(x, x, fmaf(y, y, z * z)));
    }
    __syncthreads();

    int qi = bx * 256 + tid;
    float vs = 0.f, vq = 0.f;
    if (qi < Nq) {
        const float* Qp = Q + ((size_t)b * Nq + qi) * 3;
        float qx = Qp[0], qy = Qp[1], qz = Qp[2];
        float qn = fmaf(qx, qx, fmaf(qy, qy, qz * qz));
        float best = 1e30f;
#pragma unroll 4
        for (int j = 0; j < Np; ++j) {
            float4 pt = pts[j];
            float dot = fmaf(pt.x, qx, fmaf(pt.y, qy, pt.z * qz));
            float d   = fmaf(-2.f, dot, pt.w + qn);
            d = fmaxf(d, 0.f);
            best = fminf(best, d);
        }
        vq = best;
        vs = sqrtf(best);
    }
#pragma unroll
    for (int off = 16; off; off >>= 1) {
        vs += __shfl_down_sync(0xffffffffu, vs, off);
        vq += __shfl_down_sync(0xffffffffu, vq, off);
    }
    int lane = tid & 31, wid = tid >> 5;
    if (lane == 0) { w1[wid] = vs; w2[wid] = vq; }
    __syncthreads();
    if (tid == 0) {
        float s1 = 0.f, s2 = 0.f;
#pragma unroll
        for (int k = 0; k < 8; k++) { s1 += w1[k]; s2 += w2[k]; }
        int idx = ((dir * BATCH + b) * 16 + bx) * 2;
        d_chpart[idx + 0] = s1;
        d_chpart[idx + 1] = s2;
    }
}

// ---------------------------------------------------------------------------
// PU-GAN uniform loss (numerics FROZEN — knife-edge validated; R15 exact).
// ---------------------------------------------------------------------------
template <int GDMODE>
__global__ void __launch_bounds__(256) uniform_kernel(const float* __restrict__ pcd,
                                                      const float* __restrict__ seeds,
                                                      int N, int npoint,
                                                      int nblk) {
    extern __shared__ float smem[];
    float4* cloud = (float4*)smem;
    float*  vpl   = smem + 4 * N;
    __shared__ int lists[8][52];

    float* part = (GDMODE == 0) ? d_upart1 : d_upart2;

    int b = blockIdx.y;
    int tid = threadIdx.x;
    int wid = tid >> 5, lane = tid & 31;
    const float* Pb = pcd + (size_t)b * N * 3;
    for (int i = tid; i < N; i += 256) {
        float x = Pb[3 * i], y = Pb[3 * i + 1], z = Pb[3 * i + 2];
        cloud[i] = make_float4(x, y, z, norm_asc(x, y, z));
        vpl[i] = norm_plain(x, y, z);
    }
    __syncthreads();

    int pidx = (b * nblk + blockIdx.x) * 8 + wid;
    int s = blockIdx.x * 8 + wid;
    if (s >= npoint) {
        if (lane == 0) part[pidx] = 0.f;
        return;
    }

    const float* sp = seeds + ((size_t)b * npoint + s) * 3;
    float sx = sp[0], sy = sp[1], sz = sp[2];
    float sn = norm_asc(sx, sy, sz);
    int* list = lists[wid];
    float tot = 0.f;

    const double PCT[5] = {0.004, 0.006, 0.008, 0.01, 0.012};
#pragma unroll 1
    for (int pi = 0; pi < 5; ++pi) {
        double p = PCT[pi];
        int ns = (int)((float)N * (float)p);
        double r = sqrt(p);
        float r2 = (float)(r * r);
        double expect_d = sqrt(M_PI * p / (double)ns);
        float expect = (float)expect_d;
        float denom = (float)(expect_d + 1e-8);
        float w = (float)((p * 100.0) * (p * 100.0) /
                          (5.0 * (double)BATCH * (double)npoint));

        int cnt = 0;
        for (int base = 0; base < N && cnt < ns; base += 32) {
            int i = base + lane;
            bool in = false;
            if (i < N) {
                float4 pt = cloud[i];
                float dot = dot_asc(sx, sy, sz, pt.x, pt.y, pt.z);
                float d   = sqd_ref(sn, pt.w, dot);
                in = d < r2;
            }
            unsigned bal = __ballot_sync(0xffffffffu, in);
            if (in) {
                int pos = cnt + __popc(bal & ((1u << lane) - 1u));
                if (pos < ns) list[pos] = i;
            }
            cnt += __popc(bal);
            if (cnt > ns) cnt = ns;
        }
        int c = cnt;
        __syncwarp();

        float dsum = 0.f;
        for (int k = lane; k < ns; k += 32) {
            int gi = (k < c) ? list[k] : list[0];
            float4 g = cloud[gi];
            float gn = (GDMODE == 0) ? g.w : vpl[gi];
            float nn = 1e10f;
            for (int j = 0; j < ns; ++j) {
                if (j == k) continue;
                int gj = (j < c) ? list[j] : list[0];
                float4 h = cloud[gj];
                float hn = (GDMODE == 0) ? h.w : vpl[gj];
                float dot = dot_asc(g.x, g.y, g.z, h.x, h.y, h.z);
                float d   = sqd_ref(gn, hn, dot);
                nn = fminf(nn, d);
            }
            dsum += sqrtf(fabsf(__fadd_rn(nn, 1e-8f)));
        }
#pragma unroll
        for (int off = 16; off; off >>= 1)
            dsum += __shfl_down_sync(0xffffffffu, dsum, off);
        if (lane == 0) {
            float mean_d = dsum / (float)ns;
            float df = __fadd_rn(mean_d, -expect);
            tot += (__fmul_rn(df, df) / denom) * w;
        }
        __syncwarp();
    }
    if (lane == 0) part[pidx] = tot;
}

// ---------------------------------------------------------------------------
// finalize (R15 exact).
// ---------------------------------------------------------------------------
__global__ void finalize_kernel(float* __restrict__ out) {
    int tid = threadIdx.x;
    const int base = BATCH * NP1 * 3 + BATCH * NP2 * 3;  // 61440
    if (tid < 4) {
        int b = tid;
        float e1 = 0.f, e2 = 0.f;
        for (int k = 0; k < 32; k++)  e1 += d_emdpart[b * 128 + k];
        for (int k = 0; k < 128; k++) e2 += d_emdpart[BATCH * 128 + b * 128 + k];
        out[base + 0 + b] = e1 / (float)NP1;
        out[base + 4 + b] = e2 / (float)NP2;

        const int cnts[4] = {16, 4, 16, 16};
        float cs[4], cq[4];
        for (int dir = 0; dir < 4; dir++) {
            float s = 0.f, q = 0.f;
            for (int k = 0; k < cnts[dir]; k++) {
                int idx = ((dir * BATCH + b) * 16 + k) * 2;
                s += d_chpart[idx + 0];
                q += d_chpart[idx + 1];
            }
            cs[dir] = s; cq[dir] = q;
        }
        out[base + 8 + b]  = 0.5f * (cs[0] / 4096.f + cs[1] / 1024.f);
        out[base + 12 + b] = 0.5f * (cs[2] / 4096.f + cs[3] / 4096.f);
        out[base + 16 + b] = cq[0] / 4096.f + cq[1] / 1024.f;
        out[base + 20 + b] = cq[2] / 4096.f + cq[3] / 4096.f;
    }
    if (tid == 4) {
        float u = 0.f;
        for (int i = 0; i < BATCH * 7 * 8; i++) u += d_upart1[i];
        out[base + 24] = u;
    }
    if (tid == 5) {
        float u = 0.f;
        for (int i = 0; i < BATCH * 26 * 8; i++) u += d_upart2[i];
        out[base + 25] = u;
    }
}

// ---------------------------------------------------------------------------
extern "C" void kernel_launch(void* const* d_in, const int* in_sizes, int n_in,
                              void* d_out, int out_size) {
    const float* o1 = (const float*)d_in[0];
    const float* o2 = (const float*)d_in[1];
    const float* gt = (const float*)d_in[2];
    float* out = (float*)d_out;

    cudaFuncSetAttribute(sinkf_kernel, cudaFuncAttributeMaxDynamicSharedMemorySize, 96 * 1024);
    cudaFuncSetAttribute(emddist_kernel, cudaFuncAttributeMaxDynamicSharedMemorySize, 96 * 1024);
    cudaFuncSetAttribute(nnminf_kernel, cudaFuncAttributeMaxDynamicSharedMemorySize, 72 * 1024);
    cudaFuncSetAttribute(uniform_kernel<0>, cudaFuncAttributeMaxDynamicSharedMemorySize, 96 * 1024);
    cudaFuncSetAttribute(uniform_kernel<1>, cudaFuncAttributeMaxDynamicSharedMemorySize, 96 * 1024);

    // pass-through outputs
    cudaMemcpyAsync(out, o1, (size_t)BATCH * NP1 * 3 * sizeof(float),
                    cudaMemcpyDeviceToDevice, 0);
    cudaMemcpyAsync(out + BATCH * NP1 * 3, o2,
                    (size_t)BATCH * NP2 * 3 * sizeof(float),
                    cudaMemcpyDeviceToDevice, 0);

    // FPS (seeds bit-identical): gt ascFMA; o1/o2 descFMA.
    fps3_kernel<16, 0><<<BATCH, 256>>>(gt, NP1, d_gtfps);
    fps3_kernel<4,  1><<<BATCH, 256>>>(o1, 51, d_seeds1);
    fps3_kernel<16, 1><<<BATCH, 256>>>(o2, 204, d_seeds2);

    // Fused Sinkhorn: each launch advances both chains one half-iteration.
    {
        float la1 = -(float)(0.005 * log((double)NP1));
        float la2 = -(float)(0.005 * log((double)NP2));
        size_t sm = (size_t)NP2 * 16 + 8 * 128 * 4;   // pts + red
        dim3 grid(NP1 / 128 + NP2 / 128, BATCH);      // 40 x 4
        sinkf_kernel<<<grid, 1024, sm>>>(o1, d_f1, d_gtfps, d_g1, NP1, la1,
                                         o2, d_f2, gt,      d_g2, NP2, la2, 1);
        sinkf_kernel<<<grid, 1024, sm>>>(d_gtfps, d_g1, o1, d_f1, NP1, la1,
                                         gt,      d_g2, o2, d_f2, NP2, la2, 0);
        for (int it = 1; it < 10; ++it) {
            sinkf_kernel<<<grid, 1024, sm>>>(o1, d_f1, d_gtfps, d_g1, NP1, la1,
                                             o2, d_f2, gt,      d_g2, NP2, la2, 0);
            sinkf_kernel<<<grid, 1024, sm>>>(d_gtfps, d_g1, o1, d_f1, NP1, la1,
                                             gt,      d_g2, o2, d_f2, NP2, la2, 0);
        }
        emddist_kernel<<<dim3(NP1 / 32, BATCH), 1024, (size_t)NP1 * 20>>>(
            d_gtfps, d_g1, o1, d_f1, NP1, 0);
        emddist_kernel<<<dim3(NP2 / 32, BATCH), 1024, (size_t)NP2 * 20>>>(
            gt, d_g2, o2, d_f2, NP2, 1);
    }

    // Fused Chamfer (4 directions, one launch).
    nnminf_kernel<<<dim3(52, BATCH), 256, (size_t)NP2 * 16>>>(o1, o2, gt);

    // Uniform losses: o1 matched gd; o2 mismatched gd.
    uniform_kernel<0><<<dim3(7,  BATCH), 256, (size_t)NP1 * 20>>>(o1, d_seeds1, NP1, 51, 7);
    uniform_kernel<1><<<dim3(26, BATCH), 256, (size_t)NP2 * 20>>>(o2, d_seeds2, NP2, 204, 26);

    finalize_kernel<<<1, 32>>>(out);
}